// round 6
// baseline (speedup 1.0000x reference)
#include <cuda_runtime.h>
#include <cuda_pipeline_primitives.h>
#include <math.h>

#define BB 2
#define NN 512
#define CS 128
#define CH 16
#define HH 12
#define PQ 4
#define VV 8
#define HC (HH*CH)            /* 192 */
#define CATD (HH*(CH+VV*4))   /* 576 */

// ---------------- scratch (device globals; no allocations allowed) -----------
__device__ float q_g  [BB*HH*NN*CH];
__device__ float k_g  [BB*HH*NN*CH];
__device__ float v_g  [BB*HH*NN*CH];
__device__ float qp_g [BB*HH*NN*PQ*3];
__device__ float kp_g [BB*HH*NN*PQ*3];
__device__ float vp_g [BB*HH*NN*VV*3];
__device__ float sqq_g[BB*HH*NN];
__device__ float sqk_g[BB*HH*NN];
__device__ float cat_g[BB*NN*CATD];

// ---------------- kernel 1: unified projection GEMM + rotation ---------------
// [1024 x 128] @ [128 x 1152]; 288 threads x (4 cols x 8 rows); 128 blocks = 1 wave.
#define PR 8
__global__ __launch_bounds__(288) void proj_kernel(
    const float* __restrict__ s,  const float* __restrict__ R,
    const float* __restrict__ t,
    const float* __restrict__ Wq,  const float* __restrict__ bq,
    const float* __restrict__ Wkv, const float* __restrict__ bkv,
    const float* __restrict__ Wqp, const float* __restrict__ bqp,
    const float* __restrict__ Wkvp,const float* __restrict__ bkvp)
{
    __shared__ float4 s4_sm[PR][32];        // s rows as float4
    __shared__ float  raw_sm[PR][576];      // raw point projections
    __shared__ float  Rt_sm[PR][12];
    __shared__ float  sqq_sm[PR][HH];
    __shared__ float  sqk_sm[PR][HH];

    const int tid  = threadIdx.x;
    const int row0 = blockIdx.x * PR;

    for (int idx = tid; idx < PR*32; idx += 288)
        s4_sm[idx>>5][idx&31] = ((const float4*)s)[(long)row0*32 + idx];
    if (tid < PR*12) {
        int r = tid/12, c = tid%12;
        Rt_sm[r][c] = (c < 9) ? R[(long)(row0+r)*9 + c] : t[(long)(row0+r)*3 + (c-9)];
    }
    if (tid < PR*HH) {
        sqq_sm[tid/HH][tid%HH] = 0.f;
        sqk_sm[tid/HH][tid%HH] = 0.f;
    }
    __syncthreads();

    // ---- GEMM: each thread owns 4 consecutive cols x 8 rows ----
    {
        const int col = tid * 4;           // 0..1148
        const float* Wb; const float* bb; int stride; int lcol;
        if (col < 192)      { Wb = Wq;   bb = bq;   stride = 192; lcol = col;       }
        else if (col < 576) { Wb = Wkv;  bb = bkv;  stride = 384; lcol = col - 192; }
        else if (col < 720) { Wb = Wqp;  bb = bqp;  stride = 144; lcol = col - 576; }
        else                { Wb = Wkvp; bb = bkvp; stride = 432; lcol = col - 720; }
        const int s4 = stride >> 2;
        const float4* Wp = (const float4*)Wb + (lcol >> 2);
        const float4 bias4 = __ldg((const float4*)(bb + lcol));

        float4 acc[PR];
        #pragma unroll
        for (int r = 0; r < PR; r++) acc[r] = bias4;

        #pragma unroll 2
        for (int kc = 0; kc < 32; kc++) {
            float4 sv[PR];
            #pragma unroll
            for (int r = 0; r < PR; r++) sv[r] = s4_sm[r][kc];
            #pragma unroll
            for (int qq = 0; qq < 4; qq++) {
                float4 w = __ldg(Wp + (kc*4+qq)*s4);
                #pragma unroll
                for (int r = 0; r < PR; r++) {
                    float sc = (qq==0)?sv[r].x:((qq==1)?sv[r].y:((qq==2)?sv[r].z:sv[r].w));
                    acc[r].x += w.x*sc; acc[r].y += w.y*sc;
                    acc[r].z += w.z*sc; acc[r].w += w.w*sc;
                }
            }
        }

        if (col < 192) {
            int h = col >> 4, c = col & 15;
            #pragma unroll
            for (int r = 0; r < PR; r++) {
                int row = row0 + r, b = row >> 9, n = row & 511;
                *(float4*)&q_g[((long)(b*HH+h)*NN + n)*CH + c] = acc[r];
            }
        } else if (col < 576) {
            int lc = col - 192;
            int h = lc >> 5, cc = lc & 31;
            #pragma unroll
            for (int r = 0; r < PR; r++) {
                int row = row0 + r, b = row >> 9, n = row & 511;
                long base = ((long)(b*HH+h)*NN + n)*CH;
                if (cc < 16) *(float4*)&k_g[base + cc]      = acc[r];
                else         *(float4*)&v_g[base + (cc-16)] = acc[r];
            }
        } else {
            int pc = col - 576;   // 0..575
            #pragma unroll
            for (int r = 0; r < PR; r++)
                *(float4*)&raw_sm[r][pc] = acc[r];
        }
    }
    __syncthreads();

    // ---- rotation + squared-norm pass ----
    for (int pt = tid; pt < PR*192; pt += 288) {
        const int r = pt / 192, p = pt % 192;
        const int row = row0 + r, b = row >> 9, n = row & 511;
        float d0, d1, d2; int is_qp, h, idx;
        if (p < 48) {        // qp: layout [3][48]
            d0 = raw_sm[r][p]; d1 = raw_sm[r][48+p]; d2 = raw_sm[r][96+p];
            is_qp = 1; h = p >> 2; idx = p & 3;
        } else {             // kvp: layout [3][144] at offset 144
            int pk = p - 48;
            d0 = raw_sm[r][144+pk]; d1 = raw_sm[r][288+pk]; d2 = raw_sm[r][432+pk];
            is_qp = 0; h = pk / 12; idx = pk % 12;
        }
        float x0 = Rt_sm[r][0]*d0 + Rt_sm[r][1]*d1 + Rt_sm[r][2]*d2 + Rt_sm[r][9];
        float x1 = Rt_sm[r][3]*d0 + Rt_sm[r][4]*d1 + Rt_sm[r][5]*d2 + Rt_sm[r][10];
        float x2 = Rt_sm[r][6]*d0 + Rt_sm[r][7]*d1 + Rt_sm[r][8]*d2 + Rt_sm[r][11];
        if (is_qp) {
            long base = ((long)(b*HH+h)*NN + n)*(PQ*3) + idx*3;
            qp_g[base+0] = x0; qp_g[base+1] = x1; qp_g[base+2] = x2;
            atomicAdd(&sqq_sm[r][h], x0*x0 + x1*x1 + x2*x2);
        } else if (idx < PQ) {
            long base = ((long)(b*HH+h)*NN + n)*(PQ*3) + idx*3;
            kp_g[base+0] = x0; kp_g[base+1] = x1; kp_g[base+2] = x2;
            atomicAdd(&sqk_sm[r][h], x0*x0 + x1*x1 + x2*x2);
        } else {
            long base = ((long)(b*HH+h)*NN + n)*(VV*3) + (idx-PQ)*3;
            vp_g[base+0] = x0; vp_g[base+1] = x1; vp_g[base+2] = x2;
        }
    }
    __syncthreads();
    if (tid < PR*HH) {
        int r = tid/HH, h = tid%HH;
        int row = row0 + r, b = row >> 9, n = row & 511;
        sqq_g[(long)(b*HH+h)*NN + n] = sqq_sm[r][h];
        sqk_g[(long)(b*HH+h)*NN + n] = sqk_sm[r][h];
    }
}

// ---------------- kernel 2: attention, whole-(b,h) persistent SMEM ----------
// pool layout (floats):
//   [0      .. 14336) : K+KP interleaved, row j stride 28: k[16] kp[12]
//                       (after phase A this region is reused for VP, stride 28: vp[24])
//   [14336 .. 24576) : V, row j stride 20: v[16]
#define KKP_S 28
#define V_OFF 14336
#define V_S   20
#define ATTN_SMEM_FLOATS 24576
#define ATTN_SMEM_BYTES  (ATTN_SMEM_FLOATS*4)

__global__ __launch_bounds__(256) void attn_kernel(
    const float* __restrict__ pair_mask,
    const float* __restrict__ R, const float* __restrict__ t,
    const float* __restrict__ head_weights)
{
    extern __shared__ __align__(16) float pool[];
    __shared__ float red[8][2][41];

    const int tid  = threadIdx.x;
    const int lane = tid & 31;
    const int warp = tid >> 5;
    const int b = blockIdx.z, h = blockIdx.y;
    const int i0 = blockIdx.x*16 + warp*2;
    const int bh = b*HH + h;

    const float hwv = log1pf(__expf(head_weights[h])) * 0.1360827634879543f; // sqrt(1/54)
    const float c1  = -0.5f * hwv;
    const float qs  = 0.14433756729740643f;  // 1/sqrt(48)

    const float* sqkrow = sqk_g + (long)bh*NN;
    const float* mrow0  = pair_mask + ((long)b*NN + i0)*NN;
    const float* mrow1  = mrow0 + NN;

    // ---- kick off fills: K+KP and V for the whole (b,h) ----
    {
        const float4* k4 = (const float4*)(k_g + (long)bh*NN*CH);
        for (int idx = tid; idx < 2048; idx += 256)
            __pipeline_memcpy_async(&pool[(idx>>2)*KKP_S + ((idx&3)<<2)], &k4[idx], 16);
        const float4* kp4 = (const float4*)(kp_g + (long)bh*NN*12);
        for (int idx = tid; idx < 1536; idx += 256) {
            int j = idx/3, c = idx - j*3;
            __pipeline_memcpy_async(&pool[j*KKP_S + 16 + (c<<2)], &kp4[idx], 16);
        }
        const float4* v4 = (const float4*)(v_g + (long)bh*NN*CH);
        for (int idx = tid; idx < 2048; idx += 256)
            __pipeline_memcpy_async(&pool[V_OFF + (idx>>2)*V_S + ((idx&3)<<2)], &v4[idx], 16);
    }
    __pipeline_commit();

    // ---- load + prescale queries while fills land ----
    float q0[CH], q1[CH], qp0[12], qp1[12];
    {
        const float4* qr0 = (const float4*)(q_g + ((long)bh*NN + i0)*CH);
        const float4* qr1 = (const float4*)(q_g + ((long)bh*NN + i0+1)*CH);
        #pragma unroll
        for (int c = 0; c < 4; c++) {
            float4 a = qr0[c];
            q0[4*c]=a.x*qs; q0[4*c+1]=a.y*qs; q0[4*c+2]=a.z*qs; q0[4*c+3]=a.w*qs;
            float4 d = qr1[c];
            q1[4*c]=d.x*qs; q1[4*c+1]=d.y*qs; q1[4*c+2]=d.z*qs; q1[4*c+3]=d.w*qs;
        }
        const float4* pr0 = (const float4*)(qp_g + ((long)bh*NN + i0)*12);
        const float4* pr1 = (const float4*)(qp_g + ((long)bh*NN + i0+1)*12);
        #pragma unroll
        for (int c = 0; c < 3; c++) {
            float4 a = pr0[c];
            qp0[4*c]=a.x*hwv; qp0[4*c+1]=a.y*hwv; qp0[4*c+2]=a.z*hwv; qp0[4*c+3]=a.w*hwv;
            float4 d = pr1[c];
            qp1[4*c]=d.x*hwv; qp1[4*c+1]=d.y*hwv; qp1[4*c+2]=d.z*hwv; qp1[4*c+3]=d.w*hwv;
        }
    }
    const float base0 = c1 * __ldg(&sqq_g[(long)bh*NN + i0]);
    const float base1 = c1 * __ldg(&sqq_g[(long)bh*NN + i0+1]);

    __pipeline_wait_prior(0);
    __syncthreads();

    // ================= phase A: all 512 logits, barrier-free =================
    float la0[16], la1[16];
    #pragma unroll
    for (int u = 0; u < 16; u++) {
        const int j = u*32 + lane;
        const float4* kk4 = (const float4*)(pool + j*KKP_S);
        float qk0 = 0.f, qk1 = 0.f;
        #pragma unroll
        for (int c = 0; c < 4; c++) {
            float4 kk = kk4[c];
            qk0 += q0[4*c]*kk.x + q0[4*c+1]*kk.y + q0[4*c+2]*kk.z + q0[4*c+3]*kk.w;
            qk1 += q1[4*c]*kk.x + q1[4*c+1]*kk.y + q1[4*c+2]*kk.z + q1[4*c+3]*kk.w;
        }
        #pragma unroll
        for (int c = 0; c < 3; c++) {
            float4 kk = kk4[4+c];
            qk0 += qp0[4*c]*kk.x + qp0[4*c+1]*kk.y + qp0[4*c+2]*kk.z + qp0[4*c+3]*kk.w;
            qk1 += qp1[4*c]*kk.x + qp1[4*c+1]*kk.y + qp1[4*c+2]*kk.z + qp1[4*c+3]*kk.w;
        }
        const float skc = c1 * __ldg(&sqkrow[j]);
        const float m0  = __ldg(&mrow0[j]);
        const float m1  = __ldg(&mrow1[j]);
        la0[u] = qk0 + skc + base0 + 100000.f*(m0 - 1.f);
        la1[u] = qk1 + skc + base1 + 100000.f*(m1 - 1.f);
    }
    __syncthreads();   // all warps done reading K region

    // ---- kick off VP fill into the (dead) K region ----
    {
        const float4* vp4 = (const float4*)(vp_g + (long)bh*NN*24);
        for (int idx = tid; idx < 3072; idx += 256) {
            int j = idx/6, c = idx - j*6;
            __pipeline_memcpy_async(&pool[j*KKP_S + (c<<2)], &vp4[idx], 16);
        }
    }
    __pipeline_commit();

    // ================= exact softmax (overlaps VP fill) =================
    float ls0, ls1;
    {
        float M0 = la0[0], M1 = la1[0];
        #pragma unroll
        for (int x = 1; x < 16; x++) { M0 = fmaxf(M0, la0[x]); M1 = fmaxf(M1, la1[x]); }
        #pragma unroll
        for (int o = 16; o; o >>= 1) {
            M0 = fmaxf(M0, __shfl_xor_sync(0xffffffffu, M0, o));
            M1 = fmaxf(M1, __shfl_xor_sync(0xffffffffu, M1, o));
        }
        ls0 = 0.f; ls1 = 0.f;
        #pragma unroll
        for (int x = 0; x < 16; x++) {
            la0[x] = __expf(la0[x] - M0); ls0 += la0[x];
            la1[x] = __expf(la1[x] - M1); ls1 += la1[x];
        }
    }

    // ================= phase B1: o = A @ v (V region, no barrier) ============
    {
        float av0[16], av1[16];
        #pragma unroll
        for (int x = 0; x < 16; x++) { av0[x] = 0.f; av1[x] = 0.f; }

        #pragma unroll
        for (int u = 0; u < 16; u++) {
            const int j = u*32 + lane;
            const float p0 = la0[u];
            const float p1 = la1[u];
            const float4* v4 = (const float4*)(pool + V_OFF + j*V_S);
            #pragma unroll
            for (int c = 0; c < 4; c++) {
                float4 vv = v4[c];
                av0[4*c]   += p0*vv.x; av0[4*c+1] += p0*vv.y;
                av0[4*c+2] += p0*vv.z; av0[4*c+3] += p0*vv.w;
                av1[4*c]   += p1*vv.x; av1[4*c+1] += p1*vv.y;
                av1[4*c+2] += p1*vv.z; av1[4*c+3] += p1*vv.w;
            }
        }
        float lss = ls0;
        #pragma unroll
        for (int o = 16; o; o >>= 1) lss += __shfl_xor_sync(0xffffffffu, lss, o);
        if (lane == 0) red[warp][0][40] = lss;
        lss = ls1;
        #pragma unroll
        for (int o = 16; o; o >>= 1) lss += __shfl_xor_sync(0xffffffffu, lss, o);
        if (lane == 0) red[warp][1][40] = lss;
        #pragma unroll
        for (int x = 0; x < 16; x++) {
            float v0 = av0[x], v1 = av1[x];
            #pragma unroll
            for (int o = 16; o; o >>= 1) {
                v0 += __shfl_xor_sync(0xffffffffu, v0, o);
                v1 += __shfl_xor_sync(0xffffffffu, v1, o);
            }
            if (lane == 0) { red[warp][0][x] = v0; red[warp][1][x] = v1; }
        }
    }

    __pipeline_wait_prior(0);
    __syncthreads();   // VP in place

    // ================= phase B2: o_pt = A @ vp =================
    {
        float ap0[24], ap1[24];
        #pragma unroll
        for (int x = 0; x < 24; x++) { ap0[x] = 0.f; ap1[x] = 0.f; }

        #pragma unroll
        for (int u = 0; u < 16; u++) {
            const int j = u*32 + lane;
            const float p0 = la0[u];
            const float p1 = la1[u];
            const float4* vp4 = (const float4*)(pool + j*KKP_S);
            #pragma unroll
            for (int c = 0; c < 6; c++) {
                float4 vv = vp4[c];
                ap0[4*c]   += p0*vv.x; ap0[4*c+1] += p0*vv.y;
                ap0[4*c+2] += p0*vv.z; ap0[4*c+3] += p0*vv.w;
                ap1[4*c]   += p1*vv.x; ap1[4*c+1] += p1*vv.y;
                ap1[4*c+2] += p1*vv.z; ap1[4*c+3] += p1*vv.w;
            }
        }
        #pragma unroll
        for (int x = 0; x < 24; x++) {
            float v0 = ap0[x], v1 = ap1[x];
            #pragma unroll
            for (int o = 16; o; o >>= 1) {
                v0 += __shfl_xor_sync(0xffffffffu, v0, o);
                v1 += __shfl_xor_sync(0xffffffffu, v1, o);
            }
            if (lane == 0) { red[warp][0][16+x] = v0; red[warp][1][16+x] = v1; }
        }
    }
    __syncwarp();

    // ================= finalize =================
    #pragma unroll
    for (int ii = 0; ii < 2; ii++) {
        const int i = i0 + ii;
        const float sinv = 1.f / red[warp][ii][40];
        const long rowbase = ((long)(b*NN + i))*CATD;
        if (lane < 16) {
            cat_g[rowbase + h*CH + lane] = red[warp][ii][lane] * sinv;
        } else if (lane < 24) {
            const int vv = lane - 16;
            float gx = red[warp][ii][16 + vv*3 + 0] * sinv;
            float gy = red[warp][ii][16 + vv*3 + 1] * sinv;
            float gz = red[warp][ii][16 + vv*3 + 2] * sinv;
            const float* Rr = R + ((long)(b*NN + i))*9;
            const float* tr = t + ((long)(b*NN + i))*3;
            float lx = Rr[0]*gx + Rr[3]*gy + Rr[6]*gz - tr[0];
            float ly = Rr[1]*gx + Rr[4]*gy + Rr[7]*gz - tr[1];
            float lz = Rr[2]*gx + Rr[5]*gy + Rr[8]*gz - tr[2];
            float nrm = sqrtf(lx*lx + ly*ly + lz*lz + 1e-8f);
            cat_g[rowbase + HC +   0 + h*VV + vv] = lx;
            cat_g[rowbase + HC +  96 + h*VV + vv] = ly;
            cat_g[rowbase + HC + 192 + h*VV + vv] = lz;
            cat_g[rowbase + HC + 288 + h*VV + vv] = nrm;
        }
    }
}

// ---------------- kernel 3: output projection (8 rows/block, single wave) ----
__global__ __launch_bounds__(256) void out_kernel(
    const float* __restrict__ Wout, const float* __restrict__ bout,
    float* __restrict__ out)
{
    __shared__ float csm[8*CATD];
    const int tid  = threadIdx.x;
    const int col  = tid & 127;
    const int half = tid >> 7;
    const int row0 = blockIdx.x * 8;

    for (int idx = tid; idx < 8*CATD; idx += 256)
        csm[idx] = cat_g[(long)row0*CATD + idx];
    __syncthreads();

    float acc[4] = {0.f, 0.f, 0.f, 0.f};
    const float* cb = csm + half*4*CATD;
    #pragma unroll 8
    for (int k = 0; k < CATD; k++) {
        float w = __ldg(&Wout[(long)k*CS + col]);
        #pragma unroll
        for (int r = 0; r < 4; r++) acc[r] += cb[r*CATD + k] * w;
    }
    float bb = bout[col];
    #pragma unroll
    for (int r = 0; r < 4; r++)
        out[(long)(row0 + half*4 + r)*CS + col] = acc[r] + bb;
}

// ---------------- launcher ----------------------------------------------------
extern "C" void kernel_launch(void* const* d_in, const int* in_sizes, int n_in,
                              void* d_out, int out_size)
{
    const float* s    = (const float*)d_in[0];
    const float* R    = (const float*)d_in[1];
    const float* t    = (const float*)d_in[2];
    const float* mask = (const float*)d_in[3];
    const float* Wq   = (const float*)d_in[4];
    const float* bq   = (const float*)d_in[5];
    const float* Wkv  = (const float*)d_in[6];
    const float* bkv  = (const float*)d_in[7];
    const float* Wqp  = (const float*)d_in[8];
    const float* bqp  = (const float*)d_in[9];
    const float* Wkvp = (const float*)d_in[10];
    const float* bkvp = (const float*)d_in[11];
    const float* hwts = (const float*)d_in[12];
    const float* Wout = (const float*)d_in[13];
    const float* bout = (const float*)d_in[14];
    float* out = (float*)d_out;

    cudaFuncSetAttribute(attn_kernel,
                         cudaFuncAttributeMaxDynamicSharedMemorySize,
                         ATTN_SMEM_BYTES);

    proj_kernel<<<(BB*NN)/PR, 288>>>(s, R, t, Wq, bq, Wkv, bkv, Wqp, bqp, Wkvp, bkvp);
    attn_kernel<<<dim3(NN/16, HH, BB), 256, ATTN_SMEM_BYTES>>>(mask, R, t, hwts);
    out_kernel<<<(BB*NN)/8, 256>>>(Wout, bout, out);
}

// round 7
// speedup vs baseline: 1.1089x; 1.1089x over previous
#include <cuda_runtime.h>
#include <cuda_pipeline_primitives.h>
#include <math.h>

#define BB 2
#define NN 512
#define CS 128
#define CH 16
#define HH 12
#define PQ 4
#define VV 8
#define HC (HH*CH)            /* 192 */
#define CATD (HH*(CH+VV*4))   /* 576 */

// ---------------- scratch (device globals; no allocations allowed) -----------
__device__ float q_g  [BB*HH*NN*CH];
__device__ float k_g  [BB*HH*NN*CH];
__device__ float v_g  [BB*HH*NN*CH];
__device__ float qp_g [BB*HH*NN*PQ*3];
__device__ float kp_g [BB*HH*NN*PQ*3];
__device__ float vp_g [BB*HH*NN*VV*3];
__device__ float sqq_g[BB*HH*NN];
__device__ float sqk_g[BB*HH*NN];
__device__ float cat_g[BB*NN*CATD];

// ---------------- kernel 1: projections (R3 version — best measured) --------
#define PR 4
__global__ __launch_bounds__(256) void proj_kernel(
    const float* __restrict__ s,  const float* __restrict__ R,
    const float* __restrict__ t,
    const float* __restrict__ Wq,  const float* __restrict__ bq,
    const float* __restrict__ Wkv, const float* __restrict__ bkv,
    const float* __restrict__ Wqp, const float* __restrict__ bqp,
    const float* __restrict__ Wkvp,const float* __restrict__ bkvp)
{
    __shared__ float s_sm[PR][CS];
    __shared__ float Rt_sm[PR][12];
    __shared__ float sqq_sm[PR][HH];
    __shared__ float sqk_sm[PR][HH];

    const int tid  = threadIdx.x;
    const int row0 = blockIdx.x * PR;

    for (int idx = tid; idx < PR*CS; idx += 256)
        s_sm[idx>>7][idx&127] = s[(long)row0*CS + idx];
    if (tid < PR*12) {
        int r = tid/12, c = tid%12;
        Rt_sm[r][c] = (c < 9) ? R[(long)(row0+r)*9 + c] : t[(long)(row0+r)*3 + (c-9)];
    }
    if (tid < PR*HH) {
        sqq_sm[tid/HH][tid%HH] = 0.f;
        sqk_sm[tid/HH][tid%HH] = 0.f;
    }
    __syncthreads();

    const int task = blockIdx.y*256 + tid;
    if (task < 768) {
        if (task < 576) {
            const float* W; float bias; int stride; int col;
            if (task < 192) { col = task;       W = Wq  + col; stride = HC;   bias = bq[col];  }
            else            { col = task - 192; W = Wkv + col; stride = 2*HC; bias = bkv[col]; }
            float acc[PR];
            #pragma unroll
            for (int r = 0; r < PR; r++) acc[r] = bias;
            #pragma unroll 16
            for (int k = 0; k < CS; k++) {
                float w = __ldg(&W[(long)k*stride]);
                #pragma unroll
                for (int r = 0; r < PR; r++) acc[r] += w * s_sm[r][k];
            }
            if (task < 192) {
                int h = col >> 4, c = col & 15;
                #pragma unroll
                for (int r = 0; r < PR; r++) {
                    int row = row0 + r, b = row >> 9, n = row & 511;
                    q_g[((long)(b*HH+h)*NN + n)*CH + c] = acc[r];
                }
            } else {
                int h = col >> 5, cc = col & 31;
                #pragma unroll
                for (int r = 0; r < PR; r++) {
                    int row = row0 + r, b = row >> 9, n = row & 511;
                    long base = ((long)(b*HH+h)*NN + n)*CH;
                    if (cc < 16) k_g[base + cc]        = acc[r];
                    else         v_g[base + (cc-16)]   = acc[r];
                }
            }
        } else {
            int p; const float* W; int npts; const float* bvec; int is_qp;
            if (task < 624) { p = task - 576; W = Wqp;  npts = 48;  bvec = bqp;  is_qp = 1; }
            else            { p = task - 624; W = Wkvp; npts = 144; bvec = bkvp; is_qp = 0; }
            float d0[PR], d1[PR], d2[PR];
            float b0 = bvec[0*npts+p], b1 = bvec[1*npts+p], b2 = bvec[2*npts+p];
            #pragma unroll
            for (int r = 0; r < PR; r++) { d0[r] = b0; d1[r] = b1; d2[r] = b2; }
            #pragma unroll 8
            for (int k = 0; k < CS; k++) {
                float w0 = __ldg(&W[(long)k*3*npts + 0*npts + p]);
                float w1 = __ldg(&W[(long)k*3*npts + 1*npts + p]);
                float w2 = __ldg(&W[(long)k*3*npts + 2*npts + p]);
                #pragma unroll
                for (int r = 0; r < PR; r++) {
                    float sv = s_sm[r][k];
                    d0[r] += w0*sv; d1[r] += w1*sv; d2[r] += w2*sv;
                }
            }
            #pragma unroll
            for (int r = 0; r < PR; r++) {
                int row = row0 + r, b = row >> 9, n = row & 511;
                float x0 = Rt_sm[r][0]*d0[r] + Rt_sm[r][1]*d1[r] + Rt_sm[r][2]*d2[r] + Rt_sm[r][9];
                float x1 = Rt_sm[r][3]*d0[r] + Rt_sm[r][4]*d1[r] + Rt_sm[r][5]*d2[r] + Rt_sm[r][10];
                float x2 = Rt_sm[r][6]*d0[r] + Rt_sm[r][7]*d1[r] + Rt_sm[r][8]*d2[r] + Rt_sm[r][11];
                if (is_qp) {
                    int h = p / PQ, pp = p % PQ;
                    long base = ((long)(b*HH+h)*NN + n)*(PQ*3) + pp*3;
                    qp_g[base+0] = x0; qp_g[base+1] = x1; qp_g[base+2] = x2;
                    atomicAdd(&sqq_sm[r][h], x0*x0 + x1*x1 + x2*x2);
                } else {
                    int h = p / (PQ+VV), idx = p % (PQ+VV);
                    if (idx < PQ) {
                        long base = ((long)(b*HH+h)*NN + n)*(PQ*3) + idx*3;
                        kp_g[base+0] = x0; kp_g[base+1] = x1; kp_g[base+2] = x2;
                        atomicAdd(&sqk_sm[r][h], x0*x0 + x1*x1 + x2*x2);
                    } else {
                        long base = ((long)(b*HH+h)*NN + n)*(VV*3) + (idx-PQ)*3;
                        vp_g[base+0] = x0; vp_g[base+1] = x1; vp_g[base+2] = x2;
                    }
                }
            }
        }
    }
    __syncthreads();
    if (blockIdx.y == 2 && tid < PR*HH) {
        int r = tid/HH, h = tid%HH;
        int row = row0 + r, b = row >> 9, n = row & 511;
        sqq_g[(long)(b*HH+h)*NN + n] = sqq_sm[r][h];
        sqk_g[(long)(b*HH+h)*NN + n] = sqk_sm[r][h];
    }
}

// ---------------- kernel 2: attention, fully pipelined tiles -----------------
// pool: two 5760-float buffers.
// A-phase buffer layout: kkp rows (stride 28: k16 kp12) [0:3584),
//                        msk[16][128] [3584:5632), sqk[128] [5632:5760)
// B1 buffer: v rows (stride 20) [0:2560)
// B2 buffer: vp rows (stride 28) [0:3584)
#define BUFSZ 5760
#define KKP_S 28
#define V_S   20

__global__ __launch_bounds__(256) void attn_kernel(
    const float* __restrict__ pair_mask,
    const float* __restrict__ R, const float* __restrict__ t,
    const float* __restrict__ head_weights)
{
    __shared__ __align__(16) float pool[2*BUFSZ];
    __shared__ float red[8][2][41];

    const int tid  = threadIdx.x;
    const int lane = tid & 31;
    const int warp = tid >> 5;
    const int b = blockIdx.z, h = blockIdx.y;
    const int ib0 = blockIdx.x*16;          // block's first query row
    const int i0  = ib0 + warp*2;           // this warp's two query rows
    const int bh = b*HH + h;

    const float hwv = log1pf(__expf(head_weights[h])) * 0.1360827634879543f; // sqrt(1/54)
    const float c1  = -0.5f * hwv;
    const float qs  = 0.14433756729740643f;  // 1/sqrt(48)

    const float* kbase  = k_g  + (long)bh*NN*CH;
    const float* vbase  = v_g  + (long)bh*NN*CH;
    const float* kpbase = kp_g + (long)bh*NN*12;
    const float* vpbase = vp_g + (long)bh*NN*24;

    // ---- fill helpers (as lambdas via macros) ----
#define FILL_A(jt, buf) do {                                                     \
        float* dst = pool + (buf)*BUFSZ;                                         \
        const float4* k4  = (const float4*)(kbase + (jt)*128*CH);                \
        for (int idx = tid; idx < 512; idx += 256)                               \
            __pipeline_memcpy_async(&dst[(idx>>2)*KKP_S + ((idx&3)<<2)], &k4[idx], 16); \
        const float4* kp4 = (const float4*)(kpbase + (jt)*128*12);               \
        for (int idx = tid; idx < 384; idx += 256) {                             \
            int j = idx/3, c = idx - j*3;                                        \
            __pipeline_memcpy_async(&dst[j*KKP_S + 16 + (c<<2)], &kp4[idx], 16); \
        }                                                                        \
        for (int idx = tid; idx < 512; idx += 256) {                             \
            int r = idx >> 5, c4 = idx & 31;                                     \
            const float4* mr = (const float4*)(pair_mask + ((long)(b*NN + ib0 + r))*NN + (jt)*128); \
            __pipeline_memcpy_async(&dst[3584 + r*128 + (c4<<2)], &mr[c4], 16);  \
        }                                                                        \
        if (tid < 32) {                                                          \
            const float4* sk4 = (const float4*)(sqk_g + (long)bh*NN + (jt)*128); \
            __pipeline_memcpy_async(&dst[5632 + (tid<<2)], &sk4[tid], 16);       \
        }                                                                        \
    } while (0)

#define FILL_V(jt, buf) do {                                                     \
        float* dst = pool + (buf)*BUFSZ;                                         \
        const float4* v4 = (const float4*)(vbase + (jt)*128*CH);                 \
        for (int idx = tid; idx < 512; idx += 256)                               \
            __pipeline_memcpy_async(&dst[(idx>>2)*V_S + ((idx&3)<<2)], &v4[idx], 16); \
    } while (0)

#define FILL_VP(jt, buf) do {                                                    \
        float* dst = pool + (buf)*BUFSZ;                                         \
        const float4* vp4 = (const float4*)(vpbase + (jt)*128*24);               \
        for (int idx = tid; idx < 768; idx += 256) {                             \
            int j = idx/6, c = idx - j*6;                                        \
            __pipeline_memcpy_async(&dst[j*KKP_S + (c<<2)], &vp4[idx], 16);      \
        }                                                                        \
    } while (0)

    // prologue: A tile 0
    FILL_A(0, 0);
    __pipeline_commit();

    // ---- load + prescale queries (overlaps fill) ----
    float q0[CH], q1[CH], qp0[12], qp1[12];
    {
        const float4* qr0 = (const float4*)(q_g + ((long)bh*NN + i0)*CH);
        const float4* qr1 = (const float4*)(q_g + ((long)bh*NN + i0+1)*CH);
        #pragma unroll
        for (int c = 0; c < 4; c++) {
            float4 a = qr0[c];
            q0[4*c]=a.x*qs; q0[4*c+1]=a.y*qs; q0[4*c+2]=a.z*qs; q0[4*c+3]=a.w*qs;
            float4 d = qr1[c];
            q1[4*c]=d.x*qs; q1[4*c+1]=d.y*qs; q1[4*c+2]=d.z*qs; q1[4*c+3]=d.w*qs;
        }
        const float4* pr0 = (const float4*)(qp_g + ((long)bh*NN + i0)*12);
        const float4* pr1 = (const float4*)(qp_g + ((long)bh*NN + i0+1)*12);
        #pragma unroll
        for (int c = 0; c < 3; c++) {
            float4 a = pr0[c];
            qp0[4*c]=a.x*hwv; qp0[4*c+1]=a.y*hwv; qp0[4*c+2]=a.z*hwv; qp0[4*c+3]=a.w*hwv;
            float4 d = pr1[c];
            qp1[4*c]=d.x*hwv; qp1[4*c+1]=d.y*hwv; qp1[4*c+2]=d.z*hwv; qp1[4*c+3]=d.w*hwv;
        }
    }
    const float base0 = c1 * __ldg(&sqq_g[(long)bh*NN + i0]);
    const float base1 = c1 * __ldg(&sqq_g[(long)bh*NN + i0+1]);

    float la0[16], la1[16];

    // ================= phase A =================
    #pragma unroll
    for (int jt = 0; jt < 4; jt++) {
        __pipeline_wait_prior(0);
        __syncthreads();
        if (jt < 3) { FILL_A(jt+1, (jt+1)&1); __pipeline_commit(); }
        else        { FILL_V(0, 0);           __pipeline_commit(); }

        const float* buf = pool + (jt&1)*BUFSZ;
        #pragma unroll
        for (int u = 0; u < 4; u++) {
            const int j = u*32 + lane;
            const float4* kk4 = (const float4*)(buf + j*KKP_S);
            float qk0 = 0.f, qk1 = 0.f;
            #pragma unroll
            for (int c = 0; c < 4; c++) {
                float4 kk = kk4[c];
                qk0 += q0[4*c]*kk.x + q0[4*c+1]*kk.y + q0[4*c+2]*kk.z + q0[4*c+3]*kk.w;
                qk1 += q1[4*c]*kk.x + q1[4*c+1]*kk.y + q1[4*c+2]*kk.z + q1[4*c+3]*kk.w;
            }
            #pragma unroll
            for (int c = 0; c < 3; c++) {
                float4 kk = kk4[4+c];
                qk0 += qp0[4*c]*kk.x + qp0[4*c+1]*kk.y + qp0[4*c+2]*kk.z + qp0[4*c+3]*kk.w;
                qk1 += qp1[4*c]*kk.x + qp1[4*c+1]*kk.y + qp1[4*c+2]*kk.z + qp1[4*c+3]*kk.w;
            }
            const float skc = c1 * buf[5632 + j];
            const float m0  = buf[3584 + (warp*2+0)*128 + j];
            const float m1  = buf[3584 + (warp*2+1)*128 + j];
            la0[jt*4+u] = qk0 + skc + base0 + 100000.f*(m0 - 1.f);
            la1[jt*4+u] = qk1 + skc + base1 + 100000.f*(m1 - 1.f);
        }
    }

    // ================= exact softmax (overlaps V t0 fill) =================
    float ls0, ls1;
    {
        float M0 = la0[0], M1 = la1[0];
        #pragma unroll
        for (int x = 1; x < 16; x++) { M0 = fmaxf(M0, la0[x]); M1 = fmaxf(M1, la1[x]); }
        #pragma unroll
        for (int o = 16; o; o >>= 1) {
            M0 = fmaxf(M0, __shfl_xor_sync(0xffffffffu, M0, o));
            M1 = fmaxf(M1, __shfl_xor_sync(0xffffffffu, M1, o));
        }
        ls0 = 0.f; ls1 = 0.f;
        #pragma unroll
        for (int x = 0; x < 16; x++) {
            la0[x] = __expf(la0[x] - M0); ls0 += la0[x];
            la1[x] = __expf(la1[x] - M1); ls1 += la1[x];
        }
    }

    // ================= phase B1: o = A @ v =================
    {
        float av0[16], av1[16];
        #pragma unroll
        for (int x = 0; x < 16; x++) { av0[x] = 0.f; av1[x] = 0.f; }

        #pragma unroll
        for (int jt = 0; jt < 4; jt++) {
            __pipeline_wait_prior(0);
            __syncthreads();
            if (jt < 3) { FILL_V(jt+1, (jt+1)&1); __pipeline_commit(); }
            else        { FILL_VP(0, 0);          __pipeline_commit(); }

            const float* vs = pool + (jt&1)*BUFSZ;
            #pragma unroll
            for (int u = 0; u < 4; u++) {
                const int j = u*32 + lane;
                const float p0 = la0[jt*4+u];
                const float p1 = la1[jt*4+u];
                const float4* v4 = (const float4*)(vs + j*V_S);
                #pragma unroll
                for (int c = 0; c < 4; c++) {
                    float4 vv = v4[c];
                    av0[4*c]   += p0*vv.x; av0[4*c+1] += p0*vv.y;
                    av0[4*c+2] += p0*vv.z; av0[4*c+3] += p0*vv.w;
                    av1[4*c]   += p1*vv.x; av1[4*c+1] += p1*vv.y;
                    av1[4*c+2] += p1*vv.z; av1[4*c+3] += p1*vv.w;
                }
            }
        }
        float lss = ls0;
        #pragma unroll
        for (int o = 16; o; o >>= 1) lss += __shfl_xor_sync(0xffffffffu, lss, o);
        if (lane == 0) red[warp][0][40] = lss;
        lss = ls1;
        #pragma unroll
        for (int o = 16; o; o >>= 1) lss += __shfl_xor_sync(0xffffffffu, lss, o);
        if (lane == 0) red[warp][1][40] = lss;
        #pragma unroll
        for (int x = 0; x < 16; x++) {
            float v0 = av0[x], v1 = av1[x];
            #pragma unroll
            for (int o = 16; o; o >>= 1) {
                v0 += __shfl_xor_sync(0xffffffffu, v0, o);
                v1 += __shfl_xor_sync(0xffffffffu, v1, o);
            }
            if (lane == 0) { red[warp][0][x] = v0; red[warp][1][x] = v1; }
        }
    }

    // ================= phase B2: o_pt = A @ vp =================
    {
        float ap0[24], ap1[24];
        #pragma unroll
        for (int x = 0; x < 24; x++) { ap0[x] = 0.f; ap1[x] = 0.f; }

        #pragma unroll
        for (int jt = 0; jt < 4; jt++) {
            __pipeline_wait_prior(0);
            __syncthreads();
            if (jt < 3) { FILL_VP(jt+1, (jt+1)&1); __pipeline_commit(); }

            const float* vps = pool + (jt&1)*BUFSZ;
            #pragma unroll
            for (int u = 0; u < 4; u++) {
                const int j = u*32 + lane;
                const float p0 = la0[jt*4+u];
                const float p1 = la1[jt*4+u];
                const float4* vp4 = (const float4*)(vps + j*KKP_S);
                #pragma unroll
                for (int c = 0; c < 6; c++) {
                    float4 vv = vp4[c];
                    ap0[4*c]   += p0*vv.x; ap0[4*c+1] += p0*vv.y;
                    ap0[4*c+2] += p0*vv.z; ap0[4*c+3] += p0*vv.w;
                    ap1[4*c]   += p1*vv.x; ap1[4*c+1] += p1*vv.y;
                    ap1[4*c+2] += p1*vv.z; ap1[4*c+3] += p1*vv.w;
                }
            }
        }
        #pragma unroll
        for (int x = 0; x < 24; x++) {
            float v0 = ap0[x], v1 = ap1[x];
            #pragma unroll
            for (int o = 16; o; o >>= 1) {
                v0 += __shfl_xor_sync(0xffffffffu, v0, o);
                v1 += __shfl_xor_sync(0xffffffffu, v1, o);
            }
            if (lane == 0) { red[warp][0][16+x] = v0; red[warp][1][16+x] = v1; }
        }
    }
    __syncwarp();

    // ================= finalize =================
    #pragma unroll
    for (int ii = 0; ii < 2; ii++) {
        const int i = i0 + ii;
        const float sinv = 1.f / red[warp][ii][40];
        const long rowbase = ((long)(b*NN + i))*CATD;
        if (lane < 16) {
            cat_g[rowbase + h*CH + lane] = red[warp][ii][lane] * sinv;
        } else if (lane < 24) {
            const int vv = lane - 16;
            float gx = red[warp][ii][16 + vv*3 + 0] * sinv;
            float gy = red[warp][ii][16 + vv*3 + 1] * sinv;
            float gz = red[warp][ii][16 + vv*3 + 2] * sinv;
            const float* Rr = R + ((long)(b*NN + i))*9;
            const float* tr = t + ((long)(b*NN + i))*3;
            float lx = Rr[0]*gx + Rr[3]*gy + Rr[6]*gz - tr[0];
            float ly = Rr[1]*gx + Rr[4]*gy + Rr[7]*gz - tr[1];
            float lz = Rr[2]*gx + Rr[5]*gy + Rr[8]*gz - tr[2];
            float nrm = sqrtf(lx*lx + ly*ly + lz*lz + 1e-8f);
            cat_g[rowbase + HC +   0 + h*VV + vv] = lx;
            cat_g[rowbase + HC +  96 + h*VV + vv] = ly;
            cat_g[rowbase + HC + 192 + h*VV + vv] = lz;
            cat_g[rowbase + HC + 288 + h*VV + vv] = nrm;
        }
    }
#undef FILL_A
#undef FILL_V
#undef FILL_VP
}

// ---------------- kernel 3: output projection (8 rows/block) -----------------
__global__ __launch_bounds__(256) void out_kernel(
    const float* __restrict__ Wout, const float* __restrict__ bout,
    float* __restrict__ out)
{
    __shared__ float csm[8*CATD];
    const int tid  = threadIdx.x;
    const int col  = tid & 127;
    const int half = tid >> 7;
    const int row0 = blockIdx.x * 8;

    for (int idx = tid; idx < 8*CATD; idx += 256)
        csm[idx] = cat_g[(long)row0*CATD + idx];
    __syncthreads();

    float acc[4] = {0.f, 0.f, 0.f, 0.f};
    const float* cb = csm + half*4*CATD;
    #pragma unroll 8
    for (int k = 0; k < CATD; k++) {
        float w = __ldg(&Wout[(long)k*CS + col]);
        #pragma unroll
        for (int r = 0; r < 4; r++) acc[r] += cb[r*CATD + k] * w;
    }
    float bb = bout[col];
    #pragma unroll
    for (int r = 0; r < 4; r++)
        out[(long)(row0 + half*4 + r)*CS + col] = acc[r] + bb;
}

// ---------------- launcher ----------------------------------------------------
extern "C" void kernel_launch(void* const* d_in, const int* in_sizes, int n_in,
                              void* d_out, int out_size)
{
    const float* s    = (const float*)d_in[0];
    const float* R    = (const float*)d_in[1];
    const float* t    = (const float*)d_in[2];
    const float* mask = (const float*)d_in[3];
    const float* Wq   = (const float*)d_in[4];
    const float* bq   = (const float*)d_in[5];
    const float* Wkv  = (const float*)d_in[6];
    const float* bkv  = (const float*)d_in[7];
    const float* Wqp  = (const float*)d_in[8];
    const float* bqp  = (const float*)d_in[9];
    const float* Wkvp = (const float*)d_in[10];
    const float* bkvp = (const float*)d_in[11];
    const float* hwts = (const float*)d_in[12];
    const float* Wout = (const float*)d_in[13];
    const float* bout = (const float*)d_in[14];
    float* out = (float*)d_out;

    proj_kernel<<<dim3((BB*NN)/PR, 3), 256>>>(s, R, t, Wq, bq, Wkv, bkv, Wqp, bqp, Wkvp, bkvp);
    attn_kernel<<<dim3(NN/16, HH, BB), 256>>>(mask, R, t, hwts);
    out_kernel<<<(BB*NN)/8, 256>>>(Wout, bout, out);
}

// round 8
// speedup vs baseline: 1.1290x; 1.0181x over previous
#include <cuda_runtime.h>
#include <cuda_pipeline_primitives.h>
#include <math.h>

#define BB 2
#define NN 512
#define CS 128
#define CH 16
#define HH 12
#define PQ 4
#define VV 8
#define HC (HH*CH)            /* 192 */
#define CATD (HH*(CH+VV*4))   /* 576 */

// ---------------- scratch (device globals; no allocations allowed) -----------
__device__ float q_g  [BB*HH*NN*CH];
__device__ float k_g  [BB*HH*NN*CH];
__device__ float v_g  [BB*HH*NN*CH];
__device__ float qp_g [BB*HH*NN*PQ*3];
__device__ float kp_g [BB*HH*NN*PQ*3];
__device__ float vp_g [BB*HH*NN*VV*3];
__device__ float sqq_g[BB*HH*NN];
__device__ float sqk_g[BB*HH*NN];
__device__ float cat_g[BB*NN*CATD];

// ---------------- kernel 1: projections (R3 version — best measured) --------
#define PR 4
__global__ __launch_bounds__(256) void proj_kernel(
    const float* __restrict__ s,  const float* __restrict__ R,
    const float* __restrict__ t,
    const float* __restrict__ Wq,  const float* __restrict__ bq,
    const float* __restrict__ Wkv, const float* __restrict__ bkv,
    const float* __restrict__ Wqp, const float* __restrict__ bqp,
    const float* __restrict__ Wkvp,const float* __restrict__ bkvp)
{
    __shared__ float s_sm[PR][CS];
    __shared__ float Rt_sm[PR][12];
    __shared__ float sqq_sm[PR][HH];
    __shared__ float sqk_sm[PR][HH];

    const int tid  = threadIdx.x;
    const int row0 = blockIdx.x * PR;

    for (int idx = tid; idx < PR*CS; idx += 256)
        s_sm[idx>>7][idx&127] = s[(long)row0*CS + idx];
    if (tid < PR*12) {
        int r = tid/12, c = tid%12;
        Rt_sm[r][c] = (c < 9) ? R[(long)(row0+r)*9 + c] : t[(long)(row0+r)*3 + (c-9)];
    }
    if (tid < PR*HH) {
        sqq_sm[tid/HH][tid%HH] = 0.f;
        sqk_sm[tid/HH][tid%HH] = 0.f;
    }
    __syncthreads();

    const int task = blockIdx.y*256 + tid;
    if (task < 768) {
        if (task < 576) {
            const float* W; float bias; int stride; int col;
            if (task < 192) { col = task;       W = Wq  + col; stride = HC;   bias = bq[col];  }
            else            { col = task - 192; W = Wkv + col; stride = 2*HC; bias = bkv[col]; }
            float acc[PR];
            #pragma unroll
            for (int r = 0; r < PR; r++) acc[r] = bias;
            #pragma unroll 16
            for (int k = 0; k < CS; k++) {
                float w = __ldg(&W[(long)k*stride]);
                #pragma unroll
                for (int r = 0; r < PR; r++) acc[r] += w * s_sm[r][k];
            }
            if (task < 192) {
                int h = col >> 4, c = col & 15;
                #pragma unroll
                for (int r = 0; r < PR; r++) {
                    int row = row0 + r, b = row >> 9, n = row & 511;
                    q_g[((long)(b*HH+h)*NN + n)*CH + c] = acc[r];
                }
            } else {
                int h = col >> 5, cc = col & 31;
                #pragma unroll
                for (int r = 0; r < PR; r++) {
                    int row = row0 + r, b = row >> 9, n = row & 511;
                    long base = ((long)(b*HH+h)*NN + n)*CH;
                    if (cc < 16) k_g[base + cc]        = acc[r];
                    else         v_g[base + (cc-16)]   = acc[r];
                }
            }
        } else {
            int p; const float* W; int npts; const float* bvec; int is_qp;
            if (task < 624) { p = task - 576; W = Wqp;  npts = 48;  bvec = bqp;  is_qp = 1; }
            else            { p = task - 624; W = Wkvp; npts = 144; bvec = bkvp; is_qp = 0; }
            float d0[PR], d1[PR], d2[PR];
            float b0 = bvec[0*npts+p], b1 = bvec[1*npts+p], b2 = bvec[2*npts+p];
            #pragma unroll
            for (int r = 0; r < PR; r++) { d0[r] = b0; d1[r] = b1; d2[r] = b2; }
            #pragma unroll 8
            for (int k = 0; k < CS; k++) {
                float w0 = __ldg(&W[(long)k*3*npts + 0*npts + p]);
                float w1 = __ldg(&W[(long)k*3*npts + 1*npts + p]);
                float w2 = __ldg(&W[(long)k*3*npts + 2*npts + p]);
                #pragma unroll
                for (int r = 0; r < PR; r++) {
                    float sv = s_sm[r][k];
                    d0[r] += w0*sv; d1[r] += w1*sv; d2[r] += w2*sv;
                }
            }
            #pragma unroll
            for (int r = 0; r < PR; r++) {
                int row = row0 + r, b = row >> 9, n = row & 511;
                float x0 = Rt_sm[r][0]*d0[r] + Rt_sm[r][1]*d1[r] + Rt_sm[r][2]*d2[r] + Rt_sm[r][9];
                float x1 = Rt_sm[r][3]*d0[r] + Rt_sm[r][4]*d1[r] + Rt_sm[r][5]*d2[r] + Rt_sm[r][10];
                float x2 = Rt_sm[r][6]*d0[r] + Rt_sm[r][7]*d1[r] + Rt_sm[r][8]*d2[r] + Rt_sm[r][11];
                if (is_qp) {
                    int h = p / PQ, pp = p % PQ;
                    long base = ((long)(b*HH+h)*NN + n)*(PQ*3) + pp*3;
                    qp_g[base+0] = x0; qp_g[base+1] = x1; qp_g[base+2] = x2;
                    atomicAdd(&sqq_sm[r][h], x0*x0 + x1*x1 + x2*x2);
                } else {
                    int h = p / (PQ+VV), idx = p % (PQ+VV);
                    if (idx < PQ) {
                        long base = ((long)(b*HH+h)*NN + n)*(PQ*3) + idx*3;
                        kp_g[base+0] = x0; kp_g[base+1] = x1; kp_g[base+2] = x2;
                        atomicAdd(&sqk_sm[r][h], x0*x0 + x1*x1 + x2*x2);
                    } else {
                        long base = ((long)(b*HH+h)*NN + n)*(VV*3) + (idx-PQ)*3;
                        vp_g[base+0] = x0; vp_g[base+1] = x1; vp_g[base+2] = x2;
                    }
                }
            }
        }
    }
    __syncthreads();
    if (blockIdx.y == 2 && tid < PR*HH) {
        int r = tid/HH, h = tid%HH;
        int row = row0 + r, b = row >> 9, n = row & 511;
        sqq_g[(long)(b*HH+h)*NN + n] = sqq_sm[r][h];
        sqk_g[(long)(b*HH+h)*NN + n] = sqk_sm[r][h];
    }
}

// ---------------- kernel 2: attention — tf32 MMA phase A ---------------------
// dynamic smem layout (floats):
//   [0, 4608)        buffer 0 (K+KP stride 36 / V stride 20 / VP stride 28)
//   [4608, 9216)     buffer 1
//   [9216, 17536)    logits [16][520]
//   [17536, 18112)   Q' raw [16][36]
#define BUFSZ    4608
#define KKP_S    36
#define V_S      20
#define VP_S     28
#define LOG_OFF  9216
#define LOG_S    520
#define QRAW_OFF 17536
#define QRAW_S   36
#define ATTN_SMEM_FLOATS 18112
#define ATTN_SMEM_BYTES  (ATTN_SMEM_FLOATS*4)

__device__ __forceinline__ unsigned f2tf(float x) {
    unsigned r;
    asm("cvt.rna.tf32.f32 %0, %1;" : "=r"(r) : "f"(x));
    return r;
}

__device__ __forceinline__ void mma_tf32(float* d, const unsigned* a,
                                         unsigned b0, unsigned b1) {
    asm("mma.sync.aligned.m16n8k8.row.col.f32.tf32.tf32.f32 "
        "{%0,%1,%2,%3},{%4,%5,%6,%7},{%8,%9},{%0,%1,%2,%3};"
        : "+f"(d[0]), "+f"(d[1]), "+f"(d[2]), "+f"(d[3])
        : "r"(a[0]), "r"(a[1]), "r"(a[2]), "r"(a[3]), "r"(b0), "r"(b1));
}

__global__ __launch_bounds__(256) void attn_kernel(
    const float* __restrict__ pair_mask,
    const float* __restrict__ R, const float* __restrict__ t,
    const float* __restrict__ head_weights)
{
    extern __shared__ __align__(16) float pool[];
    __shared__ float red[8][2][41];

    const int tid  = threadIdx.x;
    const int lane = tid & 31;
    const int warp = tid >> 5;
    const int b = blockIdx.z, h = blockIdx.y;
    const int ib0 = blockIdx.x*16;
    const int i0  = ib0 + warp*2;
    const int bh = b*HH + h;

    const float hwv = log1pf(__expf(head_weights[h])) * 0.1360827634879543f; // 1/sqrt(54)
    const float c1  = -0.5f * hwv;
    const float qs  = 0.14433756729740643f;  // 1/sqrt(48)

    const float* kbase  = k_g  + (long)bh*NN*CH;
    const float* vbase  = v_g  + (long)bh*NN*CH;
    const float* kpbase = kp_g + (long)bh*NN*12;
    const float* vpbase = vp_g + (long)bh*NN*24;
    const float* sqkrow = sqk_g + (long)bh*NN;
    const float* mrow0  = pair_mask + ((long)(b*NN + i0))*NN;
    const float* mrow1  = mrow0 + NN;

#define FILL_A(jt, bf) do {                                                      \
        float* dst = pool + (bf)*BUFSZ;                                          \
        const float4* k4 = (const float4*)(kbase + (jt)*128*CH);                 \
        for (int idx = tid; idx < 512; idx += 256)                               \
            __pipeline_memcpy_async(&dst[(idx>>2)*KKP_S + ((idx&3)<<2)], &k4[idx], 16); \
        const float4* kp4 = (const float4*)(kpbase + (jt)*128*12);               \
        for (int idx = tid; idx < 384; idx += 256) {                             \
            int jj = idx/3, cc = idx - jj*3;                                     \
            __pipeline_memcpy_async(&dst[jj*KKP_S + 16 + (cc<<2)], &kp4[idx], 16); \
        }                                                                        \
    } while (0)

#define FILL_V(jt, bf) do {                                                      \
        float* dst = pool + (bf)*BUFSZ;                                          \
        const float4* v4 = (const float4*)(vbase + (jt)*128*CH);                 \
        for (int idx = tid; idx < 512; idx += 256)                               \
            __pipeline_memcpy_async(&dst[(idx>>2)*V_S + ((idx&3)<<2)], &v4[idx], 16); \
    } while (0)

#define FILL_VP(jt, bf) do {                                                     \
        float* dst = pool + (bf)*BUFSZ;                                          \
        const float4* vp4 = (const float4*)(vpbase + (jt)*128*24);               \
        for (int idx = tid; idx < 768; idx += 256) {                             \
            int jj = idx/6, cc = idx - jj*6;                                     \
            __pipeline_memcpy_async(&dst[jj*VP_S + (cc<<2)], &vp4[idx], 16);     \
        }                                                                        \
    } while (0)

    // prologue: K tile 0
    FILL_A(0, 0);
    __pipeline_commit();

    // zero K pad cols 28..31 in both buffers (fills never touch them)
    if (tid < 256) {
        int bf = tid >> 7, row = tid & 127;
        float4 z = make_float4(0.f, 0.f, 0.f, 0.f);
        *(float4*)&pool[bf*BUFSZ + row*KKP_S + 28] = z;
    }
    // Q' raw (prescaled), 16 queries x 28 cols + zero pad to 32
    for (int idx = tid; idx < 16*28; idx += 256) {
        int qi = idx/28, c = idx - qi*28;
        float val;
        if (c < 16) val = q_g [((long)bh*NN + ib0 + qi)*CH + c] * qs;
        else        val = qp_g[((long)bh*NN + ib0 + qi)*12 + (c-16)] * hwv;
        pool[QRAW_OFF + qi*QRAW_S + c] = val;
    }
    if (tid < 64)
        pool[QRAW_OFF + (tid>>2)*QRAW_S + 28 + (tid&3)] = 0.f;
    __syncthreads();

    // A fragments (hi/lo split), same for all tiles
    unsigned ahi[4][4], alo[4][4];
    {
        const int r = lane >> 2, c = lane & 3;
        const float* Q = pool + QRAW_OFF;
        #pragma unroll
        for (int ks = 0; ks < 4; ks++) {
            float r00 = Q[r*QRAW_S + ks*8 + c];
            float r10 = Q[(r+8)*QRAW_S + ks*8 + c];
            float r01 = Q[r*QRAW_S + ks*8 + c + 4];
            float r11 = Q[(r+8)*QRAW_S + ks*8 + c + 4];
            ahi[ks][0] = f2tf(r00); alo[ks][0] = f2tf(r00 - __uint_as_float(ahi[ks][0]));
            ahi[ks][1] = f2tf(r10); alo[ks][1] = f2tf(r10 - __uint_as_float(ahi[ks][1]));
            ahi[ks][2] = f2tf(r01); alo[ks][2] = f2tf(r01 - __uint_as_float(ahi[ks][2]));
            ahi[ks][3] = f2tf(r11); alo[ks][3] = f2tf(r11 - __uint_as_float(ahi[ks][3]));
        }
    }
    const float base0 = c1 * __ldg(&sqq_g[(long)bh*NN + i0]);
    const float base1 = c1 * __ldg(&sqq_g[(long)bh*NN + i0+1]);

    // ================= phase A: logits via tf32 MMA =================
    #pragma unroll
    for (int jt = 0; jt < 4; jt++) {
        __pipeline_wait_prior(0);
        __syncthreads();
        if (jt < 3) FILL_A(jt+1, (jt+1)&1);
        else        FILL_V(0, 0);
        __pipeline_commit();

        const float* buf = pool + (jt&1)*BUFSZ;
        float acc0[4] = {0.f,0.f,0.f,0.f};
        float acc1[4] = {0.f,0.f,0.f,0.f};
        const int jr = warp*16 + (lane>>2);     // ntile0 row; ntile1 = jr+8
        const int kc = lane & 3;
        #pragma unroll
        for (int ks = 0; ks < 4; ks++) {
            float r0 = buf[jr*KKP_S + ks*8 + kc];
            float r1 = buf[jr*KKP_S + ks*8 + kc + 4];
            unsigned kh0 = f2tf(r0), kh1 = f2tf(r1);
            unsigned kl0 = f2tf(r0 - __uint_as_float(kh0));
            unsigned kl1 = f2tf(r1 - __uint_as_float(kh1));
            mma_tf32(acc0, ahi[ks], kh0, kh1);
            mma_tf32(acc0, ahi[ks], kl0, kl1);
            mma_tf32(acc0, alo[ks], kh0, kh1);

            float s0 = buf[(jr+8)*KKP_S + ks*8 + kc];
            float s1 = buf[(jr+8)*KKP_S + ks*8 + kc + 4];
            unsigned sh0 = f2tf(s0), sh1 = f2tf(s1);
            unsigned sl0 = f2tf(s0 - __uint_as_float(sh0));
            unsigned sl1 = f2tf(s1 - __uint_as_float(sh1));
            mma_tf32(acc1, ahi[ks], sh0, sh1);
            mma_tf32(acc1, ahi[ks], sl0, sl1);
            mma_tf32(acc1, alo[ks], sh0, sh1);
        }
        {
            float* Lg = pool + LOG_OFF;
            const int q = lane >> 2;
            const int j = jt*128 + warp*16 + (lane&3)*2;
            Lg[q*LOG_S + j]         = acc0[0];
            Lg[q*LOG_S + j + 1]     = acc0[1];
            Lg[(q+8)*LOG_S + j]     = acc0[2];
            Lg[(q+8)*LOG_S + j + 1] = acc0[3];
            Lg[q*LOG_S + j + 8]     = acc1[0];
            Lg[q*LOG_S + j + 9]     = acc1[1];
            Lg[(q+8)*LOG_S + j + 8] = acc1[2];
            Lg[(q+8)*LOG_S + j + 9] = acc1[3];
        }
    }
    __syncthreads();   // logits complete

    // ================= softmax (exact, per-warp 2 queries) =================
    float la0[16], la1[16], ls0, ls1;
    {
        const float* Lg = pool + LOG_OFF;
        #pragma unroll
        for (int u = 0; u < 16; u++) {
            const int j = u*32 + lane;
            const float skc = c1 * __ldg(&sqkrow[j]);
            la0[u] = Lg[(warp*2+0)*LOG_S + j] + skc + base0
                     + 100000.f*(__ldg(&mrow0[j]) - 1.f);
            la1[u] = Lg[(warp*2+1)*LOG_S + j] + skc + base1
                     + 100000.f*(__ldg(&mrow1[j]) - 1.f);
        }
        float M0 = la0[0], M1 = la1[0];
        #pragma unroll
        for (int x = 1; x < 16; x++) { M0 = fmaxf(M0, la0[x]); M1 = fmaxf(M1, la1[x]); }
        #pragma unroll
        for (int o = 16; o; o >>= 1) {
            M0 = fmaxf(M0, __shfl_xor_sync(0xffffffffu, M0, o));
            M1 = fmaxf(M1, __shfl_xor_sync(0xffffffffu, M1, o));
        }
        ls0 = 0.f; ls1 = 0.f;
        #pragma unroll
        for (int x = 0; x < 16; x++) {
            la0[x] = __expf(la0[x] - M0); ls0 += la0[x];
            la1[x] = __expf(la1[x] - M1); ls1 += la1[x];
        }
    }

    // ================= phase B1: o = A @ v =================
    {
        float av0[16], av1[16];
        #pragma unroll
        for (int x = 0; x < 16; x++) { av0[x] = 0.f; av1[x] = 0.f; }

        #pragma unroll
        for (int jt = 0; jt < 4; jt++) {
            __pipeline_wait_prior(0);
            __syncthreads();
            if (jt < 3) FILL_V(jt+1, (jt+1)&1);
            else        FILL_VP(0, 0);
            __pipeline_commit();

            const float* vs = pool + (jt&1)*BUFSZ;
            #pragma unroll
            for (int u = 0; u < 4; u++) {
                const int j = u*32 + lane;
                const float p0 = la0[jt*4+u];
                const float p1 = la1[jt*4+u];
                const float4* v4 = (const float4*)(vs + j*V_S);
                #pragma unroll
                for (int c = 0; c < 4; c++) {
                    float4 vv = v4[c];
                    av0[4*c]   += p0*vv.x; av0[4*c+1] += p0*vv.y;
                    av0[4*c+2] += p0*vv.z; av0[4*c+3] += p0*vv.w;
                    av1[4*c]   += p1*vv.x; av1[4*c+1] += p1*vv.y;
                    av1[4*c+2] += p1*vv.z; av1[4*c+3] += p1*vv.w;
                }
            }
        }
        float lss = ls0;
        #pragma unroll
        for (int o = 16; o; o >>= 1) lss += __shfl_xor_sync(0xffffffffu, lss, o);
        if (lane == 0) red[warp][0][40] = lss;
        lss = ls1;
        #pragma unroll
        for (int o = 16; o; o >>= 1) lss += __shfl_xor_sync(0xffffffffu, lss, o);
        if (lane == 0) red[warp][1][40] = lss;
        #pragma unroll
        for (int x = 0; x < 16; x++) {
            float v0 = av0[x], v1 = av1[x];
            #pragma unroll
            for (int o = 16; o; o >>= 1) {
                v0 += __shfl_xor_sync(0xffffffffu, v0, o);
                v1 += __shfl_xor_sync(0xffffffffu, v1, o);
            }
            if (lane == 0) { red[warp][0][x] = v0; red[warp][1][x] = v1; }
        }
    }

    // ================= phase B2: o_pt = A @ vp =================
    {
        float ap0[24], ap1[24];
        #pragma unroll
        for (int x = 0; x < 24; x++) { ap0[x] = 0.f; ap1[x] = 0.f; }

        #pragma unroll
        for (int jt = 0; jt < 4; jt++) {
            __pipeline_wait_prior(0);
            __syncthreads();
            if (jt < 3) { FILL_VP(jt+1, (jt+1)&1); __pipeline_commit(); }

            const float* vps = pool + (jt&1)*BUFSZ;
            #pragma unroll
            for (int u = 0; u < 4; u++) {
                const int j = u*32 + lane;
                const float p0 = la0[jt*4+u];
                const float p1 = la1[jt*4+u];
                const float4* vp4 = (const float4*)(vps + j*VP_S);
                #pragma unroll
                for (int c = 0; c < 6; c++) {
                    float4 vv = vp4[c];
                    ap0[4*c]   += p0*vv.x; ap0[4*c+1] += p0*vv.y;
                    ap0[4*c+2] += p0*vv.z; ap0[4*c+3] += p0*vv.w;
                    ap1[4*c]   += p1*vv.x; ap1[4*c+1] += p1*vv.y;
                    ap1[4*c+2] += p1*vv.z; ap1[4*c+3] += p1*vv.w;
                }
            }
        }
        #pragma unroll
        for (int x = 0; x < 24; x++) {
            float v0 = ap0[x], v1 = ap1[x];
            #pragma unroll
            for (int o = 16; o; o >>= 1) {
                v0 += __shfl_xor_sync(0xffffffffu, v0, o);
                v1 += __shfl_xor_sync(0xffffffffu, v1, o);
            }
            if (lane == 0) { red[warp][0][16+x] = v0; red[warp][1][16+x] = v1; }
        }
    }
    __syncwarp();

    // ================= finalize =================
    #pragma unroll
    for (int ii = 0; ii < 2; ii++) {
        const int i = i0 + ii;
        const float sinv = 1.f / red[warp][ii][40];
        const long rowbase = ((long)(b*NN + i))*CATD;
        if (lane < 16) {
            cat_g[rowbase + h*CH + lane] = red[warp][ii][lane] * sinv;
        } else if (lane < 24) {
            const int vv = lane - 16;
            float gx = red[warp][ii][16 + vv*3 + 0] * sinv;
            float gy = red[warp][ii][16 + vv*3 + 1] * sinv;
            float gz = red[warp][ii][16 + vv*3 + 2] * sinv;
            const float* Rr = R + ((long)(b*NN + i))*9;
            const float* tr = t + ((long)(b*NN + i))*3;
            float lx = Rr[0]*gx + Rr[3]*gy + Rr[6]*gz - tr[0];
            float ly = Rr[1]*gx + Rr[4]*gy + Rr[7]*gz - tr[1];
            float lz = Rr[2]*gx + Rr[5]*gy + Rr[8]*gz - tr[2];
            float nrm = sqrtf(lx*lx + ly*ly + lz*lz + 1e-8f);
            cat_g[rowbase + HC +   0 + h*VV + vv] = lx;
            cat_g[rowbase + HC +  96 + h*VV + vv] = ly;
            cat_g[rowbase + HC + 192 + h*VV + vv] = lz;
            cat_g[rowbase + HC + 288 + h*VV + vv] = nrm;
        }
    }
#undef FILL_A
#undef FILL_V
#undef FILL_VP
}

// ---------------- kernel 3: output projection (8 rows/block) -----------------
__global__ __launch_bounds__(256) void out_kernel(
    const float* __restrict__ Wout, const float* __restrict__ bout,
    float* __restrict__ out)
{
    __shared__ float csm[8*CATD];
    const int tid  = threadIdx.x;
    const int col  = tid & 127;
    const int half = tid >> 7;
    const int row0 = blockIdx.x * 8;

    for (int idx = tid; idx < 8*CATD; idx += 256)
        csm[idx] = cat_g[(long)row0*CATD + idx];
    __syncthreads();

    float acc[4] = {0.f, 0.f, 0.f, 0.f};
    const float* cb = csm + half*4*CATD;
    #pragma unroll 8
    for (int k = 0; k < CATD; k++) {
        float w = __ldg(&Wout[(long)k*CS + col]);
        #pragma unroll
        for (int r = 0; r < 4; r++) acc[r] += cb[r*CATD + k] * w;
    }
    float bb = bout[col];
    #pragma unroll
    for (int r = 0; r < 4; r++)
        out[(long)(row0 + half*4 + r)*CS + col] = acc[r] + bb;
}

// ---------------- launcher ----------------------------------------------------
extern "C" void kernel_launch(void* const* d_in, const int* in_sizes, int n_in,
                              void* d_out, int out_size)
{
    const float* s    = (const float*)d_in[0];
    const float* R    = (const float*)d_in[1];
    const float* t    = (const float*)d_in[2];
    const float* mask = (const float*)d_in[3];
    const float* Wq   = (const float*)d_in[4];
    const float* bq   = (const float*)d_in[5];
    const float* Wkv  = (const float*)d_in[6];
    const float* bkv  = (const float*)d_in[7];
    const float* Wqp  = (const float*)d_in[8];
    const float* bqp  = (const float*)d_in[9];
    const float* Wkvp = (const float*)d_in[10];
    const float* bkvp = (const float*)d_in[11];
    const float* hwts = (const float*)d_in[12];
    const float* Wout = (const float*)d_in[13];
    const float* bout = (const float*)d_in[14];
    float* out = (float*)d_out;

    cudaFuncSetAttribute(attn_kernel,
                         cudaFuncAttributeMaxDynamicSharedMemorySize,
                         ATTN_SMEM_BYTES);

    proj_kernel<<<dim3((BB*NN)/PR, 3), 256>>>(s, R, t, Wq, bq, Wkv, bkv, Wqp, bqp, Wkvp, bkvp);
    attn_kernel<<<dim3(NN/16, HH, BB), 256, ATTN_SMEM_BYTES>>>(mask, R, t, hwts);
    out_kernel<<<(BB*NN)/8, 256>>>(Wout, bout, out);
}